// round 4
// baseline (speedup 1.0000x reference)
#include <cuda_runtime.h>
#include <cuda_bf16.h>

#define TT    111
#define NCTA  128

// ---- shared memory layout (float offsets) ----
// W4   [4][16][128] float4 @ 0        (k-minor: float4 = w[gp][4kb..4kb+3])  131072 B
// Bsm  [4][128]            @ 32768    (bih+bhh, native gate-major)
// WaS  [32]                @ 33280
// B1S  [32]                @ 33312
// W1S  [32][32]            @ 33344
// W2S  [32][3]             @ 34368
// MS   [4]                 @ 34464    (ba, b2[0..2])
// A    [8 warps][8 rows][160] @ 34496 (slot s at col s*32; slot0=x, slot1..4=h l0..l3)
// Csm  [8 warps][4][8][32] @ 44736
#define SMEM_FLOATS 52928
#define SMEM_BYTES  (SMEM_FLOATS * 4)

typedef unsigned long long u64;

__device__ __forceinline__ u64 pk0() {
    u64 r; asm("mov.b64 %0, {%1,%1};" : "=l"(r) : "f"(0.f)); return r;
}
__device__ __forceinline__ u64 ffma2(u64 a, u64 b, u64 c) {
    u64 d; asm("fma.rn.f32x2 %0, %1, %2, %3;" : "=l"(d) : "l"(a), "l"(b), "l"(c));
    return d;
}
__device__ __forceinline__ float red2(u64 v) {
    float a, b; asm("mov.b64 {%0,%1}, %2;" : "=f"(a), "=f"(b) : "l"(v));
    return a + b;
}
// sigmoid: 1/(1+e^-x), exp via __expf (EX2, ~2ulp). tanh = 2*sig(2x)-1 (overflow-graceful).
__device__ __forceinline__ float fsig(float x) {
    return __fdividef(1.f, 1.f + __expf(-x));
}
__device__ __forceinline__ float ftanh(float x) {
    float s = __fdividef(1.f, 1.f + __expf(-2.f * x));
    return fmaf(2.f, s, -1.f);
}

extern "C" __global__ void __launch_bounds__(256, 1)
lstm_fused_kernel(const int* __restrict__ x, const float* __restrict__ emb,
                  const float* __restrict__ Wih, const float* __restrict__ Whh,
                  const float* __restrict__ bih, const float* __restrict__ bhh,
                  const float* __restrict__ Wa, const float* __restrict__ ba,
                  const float* __restrict__ W1, const float* __restrict__ b1,
                  const float* __restrict__ W2, const float* __restrict__ b2,
                  float* __restrict__ out)
{
    extern __shared__ float sm[];
    float4* W4  = (float4*)sm;
    float*  Bsm = sm + 32768;
    float*  WaS = sm + 33280;
    float*  B1S = sm + 33312;
    float*  W1S = sm + 33344;
    float*  W2S = sm + 34368;
    float*  MS  = sm + 34464;
    float*  A0  = sm + 34496;
    float*  C0  = sm + 44736;

    const int tid  = threadIdx.x;
    const int w    = tid >> 5;
    const int lane = tid & 31;
    const int cta  = blockIdx.x;

    // ---- stage weights: W4[(l*16+kb)*128 + gp] = float4 of w[gp][4kb..4kb+3] ----
    for (int d = tid; d < 8192; d += 256) {
        int gp = d & 127, kb = (d >> 7) & 15, l = d >> 11;
        float4 v;
        if (kb < 8) v = *(const float4*)(Wih + (l * 128 + gp) * 32 + kb * 4);
        else        v = *(const float4*)(Whh + (l * 128 + gp) * 32 + (kb - 8) * 4);
        W4[d] = v;
    }
    for (int i = tid; i < 512; i += 256)
        Bsm[i] = bih[i] + bhh[i];
    if (tid < 32) { WaS[tid] = Wa[tid]; B1S[tid] = b1[tid]; }
    for (int i = tid; i < 1024; i += 256) W1S[i] = W1[i];
    if (tid < 96) W2S[tid] = W2[tid];
    if (tid == 0) { MS[0] = ba[0]; MS[1] = b2[0]; MS[2] = b2[1]; MS[3] = b2[2]; }
    for (int i = tid; i < 8 * 1280; i += 256) A0[i] = 0.f;
    for (int i = tid; i < 8 * 1024; i += 256) C0[i] = 0.f;
    __syncthreads();
    // ---- warps fully independent from here (each owns 8 batch rows) ----

    float* Aw = A0 + w * 1280;   // [8 rows][160]
    float* Cw = C0 + w * 1024;   // [4 l][8 rows][32]

    const float waL = WaS[lane];
    const float baS = MS[0];
    float ctx[8], se[8];
#pragma unroll
    for (int r = 0; r < 8; ++r) { ctx[r] = 0.f; se[r] = 0.f; }

    // x-index prefetch: lanes 0..7 hold the indices of their row
    const int xrow = cta * 64 + w * 8 + (lane & 7);
    int xi0 = 0, xnext = 0, xfut = 0;
    if (lane < 8) { xi0 = x[xrow * TT]; xnext = x[xrow * TT + 1]; }
    // emb for t=0 into slot0
#pragma unroll
    for (int rr = 0; rr < 8; ++rr) {
        int xv = __shfl_sync(0xffffffffu, xi0, rr);
        Aw[rr * 160 + lane] = emb[xv * 32 + lane];
    }
    __syncwarp();

    float pv0[8];

    for (int t = 0; t < TT; ++t) {
        for (int l = 0; l < 4; ++l) {
            const float4* wpl = W4 + l * 2048 + lane;   // + kb*128 + g*32
            const float*  rb  = Aw + l * 32;            // + r*160 + kb*4
            u64 acc[32];
            u64 z0 = pk0();
#pragma unroll
            for (int i = 0; i < 32; ++i) acc[i] = z0;

#pragma unroll
            for (int kb = 0; kb < 16; ++kb) {
                ulonglong2 wq[4];
#pragma unroll
                for (int g = 0; g < 4; ++g)
                    wq[g] = *(const ulonglong2*)(wpl + kb * 128 + g * 32);
                ulonglong2 xq[8];
#pragma unroll
                for (int r = 0; r < 8; ++r)
                    xq[r] = *(const ulonglong2*)(rb + r * 160 + kb * 4);
#pragma unroll
                for (int r = 0; r < 8; ++r)
#pragma unroll
                    for (int g = 0; g < 4; ++g)
                        acc[g * 8 + r] = ffma2(wq[g].x, xq[r].x, acc[g * 8 + r]);
#pragma unroll
                for (int r = 0; r < 8; ++r)
#pragma unroll
                    for (int g = 0; g < 4; ++g)
                        acc[g * 8 + r] = ffma2(wq[g].y, xq[r].y, acc[g * 8 + r]);
            }

            const float bi = Bsm[l * 128 + lane];
            const float bf = Bsm[l * 128 + 32 + lane];
            const float bg = Bsm[l * 128 + 64 + lane];
            const float bo = Bsm[l * 128 + 96 + lane];
#pragma unroll
            for (int r = 0; r < 8; ++r) {
                float zi = red2(acc[0 * 8 + r]) + bi;
                float zf = red2(acc[1 * 8 + r]) + bf;
                float zg = red2(acc[2 * 8 + r]) + bg;
                float zo = red2(acc[3 * 8 + r]) + bo;
                float c  = Cw[l * 256 + r * 32 + lane];
                c = fsig(zf) * c + fsig(zi) * ftanh(zg);
                float h = fsig(zo) * ftanh(c);
                Cw[l * 256 + r * 32 + lane] = c;
                Aw[r * 160 + (l + 1) * 32 + lane] = h;
            }
            __syncwarp();

            if (l == 0 && t + 1 < TT) {
                // prefetch next step's embedding (hidden under layers 1..3)
#pragma unroll
                for (int rr = 0; rr < 8; ++rr) {
                    int xv = __shfl_sync(0xffffffffu, xnext, rr);
                    pv0[rr] = emb[xv * 32 + lane];
                }
                xfut = 0;
                if (lane < 8 && t + 2 < TT) xfut = x[xrow * TT + t + 2];
            }
        }

        // streaming attention over slot4 h (scores tiny: no max-subtract)
#pragma unroll
        for (int r = 0; r < 8; ++r) {
            float h3 = Aw[r * 160 + 128 + lane];
            float p = h3 * waL;
            p += __shfl_xor_sync(0xffffffffu, p, 16);
            p += __shfl_xor_sync(0xffffffffu, p, 8);
            p += __shfl_xor_sync(0xffffffffu, p, 4);
            p += __shfl_xor_sync(0xffffffffu, p, 2);
            p += __shfl_xor_sync(0xffffffffu, p, 1);
            float e = __expf(p + baS);
            se[r] += e;
            ctx[r] = fmaf(e, h3, ctx[r]);
        }
        if (t + 1 < TT) {
#pragma unroll
            for (int rr = 0; rr < 8; ++rr) Aw[rr * 160 + lane] = pv0[rr];
            xnext = xfut;
            __syncwarp();
        }
    }

    // ---- head (per warp, scratch reuses Aw: 512 floats needed, 1280 avail) ----
    float* scr = Aw;
#pragma unroll
    for (int r = 0; r < 8; ++r) scr[r * 32 + lane] = __fdividef(ctx[r], se[r]);
    __syncwarp();
    float hidv[8];
#pragma unroll
    for (int r = 0; r < 8; ++r) {
        float a = B1S[lane];
#pragma unroll
        for (int u = 0; u < 32; ++u) a = fmaf(scr[r * 32 + u], W1S[u * 32 + lane], a);
        hidv[r] = ftanh(a);
    }
    __syncwarp();
#pragma unroll
    for (int r = 0; r < 8; ++r) scr[256 + r * 32 + lane] = hidv[r];
    __syncwarp();
    int rr = lane >> 2, kq = lane & 3;
    if (kq < 3) {
        float a = MS[1 + kq];
#pragma unroll
        for (int j = 0; j < 32; ++j) a = fmaf(scr[256 + rr * 32 + j], W2S[j * 3 + kq], a);
        out[(cta * 64 + w * 8 + rr) * 3 + kq] = a;
    }
}

extern "C" void kernel_launch(void* const* d_in, const int* in_sizes, int n_in,
                              void* d_out, int out_size) {
    (void)in_sizes; (void)n_in; (void)out_size;
    const int*   x   = (const int*)d_in[0];
    const float* emb = (const float*)d_in[1];
    const float* Wih = (const float*)d_in[2];
    const float* Whh = (const float*)d_in[3];
    const float* bih = (const float*)d_in[4];
    const float* bhh = (const float*)d_in[5];
    const float* Wa  = (const float*)d_in[6];
    const float* ba  = (const float*)d_in[7];
    const float* W1  = (const float*)d_in[8];
    const float* b1  = (const float*)d_in[9];
    const float* W2  = (const float*)d_in[10];
    const float* b2  = (const float*)d_in[11];
    float* out = (float*)d_out;

    cudaFuncSetAttribute(lstm_fused_kernel,
                         cudaFuncAttributeMaxDynamicSharedMemorySize, SMEM_BYTES);
    lstm_fused_kernel<<<NCTA, 256, SMEM_BYTES>>>(x, emb, Wih, Whh, bih, bhh,
                                                 Wa, ba, W1, b1, W2, b2, out);
}